// round 6
// baseline (speedup 1.0000x reference)
#include <cuda_runtime.h>
#include <cuda_bf16.h>
#include <cstdint>

// ============================================================================
// QuadraticConv2D via mma.sync (HMMA) bf16 split GEMM, software-pipelined:
//   - double-buffered A (SMEM) and B (SMEM via cp.async), 1 barrier per pair
//   - ldmatrix.x4.trans for B (2 n-tiles per instruction)
// out[m,o] = sum_{p=(i,j)} sum_c S_i[m,c]*S_j[m,c] * W[p,c,o]
// ============================================================================

#define HW     56
#define CH     64
#define OD     128
#define NPOS   (8 * 56 * 56)      // 25088
#define MT     64                 // M rows per CTA
#define NTILES (NPOS / MT)        // 392
#define BDIM   128
#define NPAIRS 55

#define ASTR   144                // A row stride bytes
#define BSTR   272                // B row stride bytes

// SMEM layout (bytes)
#define ABUF_SZ   9216            // 64 x 144
#define A_OFF(b)  ((b) * (2 * ABUF_SZ))          // hi at +0, lo at +ABUF_SZ
#define BBUF_SZ   17408           // 64 x 272
#define B_OFF(b)  (36864 + (b) * (2 * BBUF_SZ))  // hi at +0, lo at +BBUF_SZ
#define MB_OFF    106496
#define MK_OFF    106752
#define SMEM_TOTAL 107008

// pre-split weights, padded layout [p][c*136 + o] bf16
__device__ __align__(16) __nv_bfloat16 g_Bhi[NPAIRS][CH * (BSTR / 2)];
__device__ __align__(16) __nv_bfloat16 g_Blo[NPAIRS][CH * (BSTR / 2)];

__constant__ unsigned char cII[55] = {
    0,0,0,0,0,0,0,0,0,0, 1,1,1,1,1,1,1,1,1, 2,2,2,2,2,2,2,2,
    3,3,3,3,3,3,3, 4,4,4,4,4,4, 5,5,5,5,5, 6,6,6,6, 7,7,7, 8,8, 9};
__constant__ unsigned char cJJ[55] = {
    0,1,2,3,4,5,6,7,8,9, 1,2,3,4,5,6,7,8,9, 2,3,4,5,6,7,8,9,
    3,4,5,6,7,8,9, 4,5,6,7,8,9, 5,6,7,8,9, 6,7,8,9, 7,8,9, 8,9, 9};

__device__ __forceinline__ uint32_t smem_to_u32(const void* p) {
    uint32_t a;
    asm("{ .reg .u64 t; cvta.to.shared.u64 t, %1; cvt.u32.u64 %0, t; }"
        : "=r"(a) : "l"(p));
    return a;
}

#define LDSM_X4(r, addr) \
    asm volatile("ldmatrix.sync.aligned.m8n8.x4.shared.b16 {%0,%1,%2,%3}, [%4];" \
                 : "=r"((r)[0]), "=r"((r)[1]), "=r"((r)[2]), "=r"((r)[3]) \
                 : "r"(addr))
#define LDSM_X4T(r, addr) \
    asm volatile("ldmatrix.sync.aligned.m8n8.x4.trans.shared.b16 {%0,%1,%2,%3}, [%4];" \
                 : "=r"((r)[0]), "=r"((r)[1]), "=r"((r)[2]), "=r"((r)[3]) \
                 : "r"(addr))
#define CP_ASYNC16(dst, src) \
    asm volatile("cp.async.cg.shared.global [%0], [%1], 16;" \
                 :: "r"(dst), "l"(src) : "memory")
#define CP_COMMIT() asm volatile("cp.async.commit_group;" ::: "memory")
#define CP_WAIT0()  asm volatile("cp.async.wait_group 0;" ::: "memory")

__device__ __forceinline__ void mma_bf16(float* c, const uint32_t* a, const uint32_t* b) {
    asm volatile(
        "mma.sync.aligned.m16n8k16.row.col.f32.bf16.bf16.f32 "
        "{%0,%1,%2,%3}, {%4,%5,%6,%7}, {%8,%9}, {%0,%1,%2,%3};"
        : "+f"(c[0]), "+f"(c[1]), "+f"(c[2]), "+f"(c[3])
        : "r"(a[0]), "r"(a[1]), "r"(a[2]), "r"(a[3]), "r"(b[0]), "r"(b[1]));
}

// ---------------------------------------------------------------------------
__global__ void prep_weights(const float* __restrict__ wt) {
    int idx = blockIdx.x * blockDim.x + threadIdx.x;
    if (idx >= NPAIRS * CH * OD) return;
    int p = idx / (CH * OD);
    int r = idx - p * CH * OD;
    int c = r / OD;
    int o = r - c * OD;
    float w = wt[(p * CH + c) * OD + o];
    __nv_bfloat16 h = __float2bfloat16(w);
    __nv_bfloat16 l = __float2bfloat16(w - __bfloat162float(h));
    g_Bhi[p][c * (BSTR / 2) + o] = h;
    g_Blo[p][c * (BSTR / 2) + o] = l;
}

// ---------------------------------------------------------------------------
__global__ void __launch_bounds__(BDIM, 2)
qconv_hmma(const float* __restrict__ in, float* __restrict__ out) {
    extern __shared__ unsigned char smem[];
    const uint32_t sb = smem_to_u32(smem);
    int* mbase_s = (int*)(smem + MB_OFF);
    int* mmask_s = (int*)(smem + MK_OFF);

    const int tid  = threadIdx.x;
    const int wid  = tid >> 5;
    const int lane = tid & 31;
    const int gm0  = blockIdx.x * MT;

    if (tid < MT) {
        int gm  = gm0 + tid;
        int b   = gm / (HW * HW);
        int rem = gm - b * HW * HW;
        int h   = rem / HW;
        int w   = rem - h * HW;
        mbase_s[tid] = ((b * HW + (h - 1)) * HW + (w - 1)) * CH;
        int mask = 0;
        #pragma unroll
        for (int kk = 0; kk < 9; kk++) {
            int hh = h + kk / 3 - 1, ww = w + kk % 3 - 1;
            if (hh >= 0 && hh < HW && ww >= 0 && ww < HW) mask |= (1 << kk);
        }
        mmask_s[tid] = mask;
    }
    __syncthreads();

    // A-gen mapping (fixed per thread)
    const int am   = tid >> 1;
    const int c0   = (tid & 1) * 32;
    const int base = mbase_s[am];
    const int mask = mmask_s[am];

    // GEMM mapping: warps 2(M) x 2(N); warp tile 32 x 64
    const int m0 = (wid >> 1) * 32;
    const int n0 = (wid & 1) * 64;
    const uint32_t aoff = (uint32_t)((m0 + (lane & 15)) * ASTR + (lane >> 4) * 16);
    // x4.trans: lanes 0-15 -> n-tile nt (k 0-7 / 8-15), lanes 16-31 -> nt+1
    const uint32_t boff = (uint32_t)((lane & 15) * BSTR + (n0 + ((lane >> 4) & 1) * 8) * 2);

    float acc[2][8][4];
    #pragma unroll
    for (int mt = 0; mt < 2; mt++)
        #pragma unroll
        for (int nt = 0; nt < 8; nt++)
            #pragma unroll
            for (int q = 0; q < 4; q++) acc[mt][nt][q] = 0.f;

    // ---------------- helpers as lambdas ----------------
    auto stage_B = [&](int p, int buf) {
        const char* sh = (const char*)g_Bhi[p];
        const char* sl = (const char*)g_Blo[p];
        const uint32_t dh = sb + B_OFF(buf);
        const uint32_t dl = dh + BBUF_SZ;
        #pragma unroll
        for (int t = 0; t < 9; t++) {
            int x = tid + t * BDIM;          // 16B chunks, 1088 per half
            if (x < BBUF_SZ / 16) {
                CP_ASYNC16(dh + x * 16, sh + x * 16);
                CP_ASYNC16(dl + x * 16, sl + x * 16);
            }
        }
        CP_COMMIT();
    };

    auto gen_A = [&](int p, int buf) {
        const int i = cII[p], j = cJJ[p];
        const int kj = j - 1, ki = i - 1;
        const int offj = (j > 0) ? ((kj / 3) * HW + (kj % 3)) * CH : 0;
        const int offi = (i > 0) ? ((ki / 3) * HW + (ki % 3)) * CH : 0;
        const bool vj = (j == 0) || ((mask >> kj) & 1);
        const bool vi = (i == 0) || ((mask >> ki) & 1);
        unsigned char* ahi = smem + A_OFF(buf);
        unsigned char* alo = ahi + ABUF_SZ;
        #pragma unroll
        for (int g = 0; g < 8; g++) {
            const int c = c0 + g * 4;
            float4 sj, si;
            if (j == 0)   sj = make_float4(1.f, 1.f, 1.f, 1.f);
            else if (vj)  sj = *(const float4*)(in + base + offj + c);
            else          sj = make_float4(0.f, 0.f, 0.f, 0.f);
            if (i == 0)   si = make_float4(1.f, 1.f, 1.f, 1.f);
            else if (vi)  si = *(const float4*)(in + base + offi + c);
            else          si = make_float4(0.f, 0.f, 0.f, 0.f);

            float a0 = si.x * sj.x, a1 = si.y * sj.y;
            float a2 = si.z * sj.z, a3 = si.w * sj.w;
            __nv_bfloat16 h0 = __float2bfloat16(a0), h1 = __float2bfloat16(a1);
            __nv_bfloat16 h2 = __float2bfloat16(a2), h3 = __float2bfloat16(a3);
            __nv_bfloat16 l0 = __float2bfloat16(a0 - __bfloat162float(h0));
            __nv_bfloat16 l1 = __float2bfloat16(a1 - __bfloat162float(h1));
            __nv_bfloat16 l2 = __float2bfloat16(a2 - __bfloat162float(h2));
            __nv_bfloat16 l3 = __float2bfloat16(a3 - __bfloat162float(h3));
            __nv_bfloat162 hA = __halves2bfloat162(h0, h1);
            __nv_bfloat162 hB = __halves2bfloat162(h2, h3);
            __nv_bfloat162 lA = __halves2bfloat162(l0, l1);
            __nv_bfloat162 lB = __halves2bfloat162(l2, l3);
            const unsigned off = (unsigned)(am * ASTR + c * 2);
            *(uint2*)(ahi + off) = make_uint2(*(unsigned*)&hA, *(unsigned*)&hB);
            *(uint2*)(alo + off) = make_uint2(*(unsigned*)&lA, *(unsigned*)&lB);
        }
    };

    // ---------------- prologue ----------------
    stage_B(0, 0);
    gen_A(0, 0);

    // ---------------- main pipelined loop ----------------
    for (int p = 0; p < NPAIRS; p++) {
        const int buf = p & 1;
        CP_WAIT0();            // B(p) landed
        __syncthreads();       // A(p) + B(p) visible; prev MMAs done with buf^1

        if (p + 1 < NPAIRS) {
            stage_B(p + 1, buf ^ 1);   // async, overlaps MMA(p)
            gen_A(p + 1, buf ^ 1);     // LDG/CVT/STS, overlaps other warps' MMA
        }

        // ---- MMA(p): 4 k16-steps, B via x4.trans (2 n-tiles per load) ----
        const uint32_t abase = sb + A_OFF(buf) + aoff;
        const uint32_t bbase = sb + B_OFF(buf) + boff;
        #pragma unroll
        for (int kk = 0; kk < 4; kk++) {
            uint32_t ah0[4], ah1[4], al0[4], al1[4];
            const uint32_t ab = abase + kk * 32;
            LDSM_X4(ah0, ab);
            LDSM_X4(ah1, ab + 16 * ASTR);
            LDSM_X4(al0, ab + ABUF_SZ);
            LDSM_X4(al1, ab + ABUF_SZ + 16 * ASTR);
            const uint32_t bb = bbase + kk * 16 * BSTR;
            #pragma unroll
            for (int nt = 0; nt < 8; nt += 2) {
                uint32_t bh[4], bl[4];
                LDSM_X4T(bh, bb + nt * 16);
                mma_bf16(acc[0][nt],     ah0, bh);
                mma_bf16(acc[1][nt],     ah1, bh);
                mma_bf16(acc[0][nt + 1], ah0, bh + 2);
                mma_bf16(acc[1][nt + 1], ah1, bh + 2);
                mma_bf16(acc[0][nt],     al0, bh);
                mma_bf16(acc[1][nt],     al1, bh);
                mma_bf16(acc[0][nt + 1], al0, bh + 2);
                mma_bf16(acc[1][nt + 1], al1, bh + 2);
                LDSM_X4T(bl, bb + BBUF_SZ + nt * 16);
                mma_bf16(acc[0][nt],     ah0, bl);
                mma_bf16(acc[1][nt],     ah1, bl);
                mma_bf16(acc[0][nt + 1], ah0, bl + 2);
                mma_bf16(acc[1][nt + 1], ah1, bl + 2);
            }
        }
    }

    // ---------------- epilogue ----------------
    float* op = out + (size_t)gm0 * OD;
    const int rr = lane >> 2;
    const int cc = (lane & 3) * 2;
    #pragma unroll
    for (int mt = 0; mt < 2; mt++) {
        #pragma unroll
        for (int nt = 0; nt < 8; nt++) {
            const int r0 = m0 + mt * 16 + rr;
            const int cn = n0 + nt * 8 + cc;
            *(float2*)(op + (size_t)r0 * OD + cn) =
                make_float2(acc[mt][nt][0], acc[mt][nt][1]);
            *(float2*)(op + (size_t)(r0 + 8) * OD + cn) =
                make_float2(acc[mt][nt][2], acc[mt][nt][3]);
        }
    }
}

// ---------------------------------------------------------------------------
extern "C" void kernel_launch(void* const* d_in, const int* in_sizes, int n_in,
                              void* d_out, int out_size) {
    const float* in = (const float*)d_in[0];
    const float* wt = (const float*)d_in[1];
    if (n_in >= 2 && in_sizes[0] == NPAIRS * CH * OD) {
        const float* t = in; in = wt; wt = t;
    }
    float* out = (float*)d_out;

    prep_weights<<<(NPAIRS * CH * OD + 255) / 256, 256>>>(wt);

    cudaFuncSetAttribute(qconv_hmma,
                         cudaFuncAttributeMaxDynamicSharedMemorySize, SMEM_TOTAL);
    qconv_hmma<<<NTILES, BDIM, SMEM_TOTAL>>>(in, out);
}

// round 7
// speedup vs baseline: 1.2627x; 1.2627x over previous
#include <cuda_runtime.h>
#include <cuda_bf16.h>
#include <cstdint>

// ============================================================================
// QuadraticConv2D via warp-specialized HMMA bf16 split GEMM.
//   warps 0-3: consumers — pure ldmatrix + mma.sync, register accumulators
//   warps 4-7: producers — cp.async B tiles + on-the-fly quad-feature A tiles
//   double-buffered SMEM, named-barrier FULL/EMPTY handshake, 1 pair ahead.
// out[m,o] = sum_{p=(i,j)} sum_c S_i[m,c]*S_j[m,c] * W[p,c,o]
// fp32 split x = hi + lo (bf16); per product: hi*hi + hi*lo + lo*hi.
// ============================================================================

#define HW     56
#define CH     64
#define OD     128
#define NPOS   (8 * 56 * 56)      // 25088
#define MT     64                 // M rows per CTA
#define NTILES (NPOS / MT)        // 392
#define BDIM   256                // 4 consumer + 4 producer warps
#define NPAIRS 55

#define ASTR   144                // A row stride bytes
#define BSTR   272                // B row stride bytes

// SMEM layout (bytes)
#define ABUF_SZ   9216            // 64 x 144 (one of hi/lo)
#define A_OFF(b)  ((b) * (2 * ABUF_SZ))          // hi +0, lo +ABUF_SZ
#define BBUF_SZ   17408           // 64 x 272
#define B_OFF(b)  (36864 + (b) * (2 * BBUF_SZ))  // hi +0, lo +BBUF_SZ
#define MB_OFF    106496
#define MK_OFF    106752
#define SMEM_TOTAL 107008

// named barriers (0 reserved for __syncthreads)
#define BAR_FULL0  1
#define BAR_FULL1  2
#define BAR_EMPTY0 3
#define BAR_EMPTY1 4
#define BAR_SYNC(id)   asm volatile("bar.sync %0, %1;"   :: "r"(id), "r"(BDIM) : "memory")
#define BAR_ARRIVE(id) asm volatile("bar.arrive %0, %1;" :: "r"(id), "r"(BDIM) : "memory")

// pre-split weights, padded layout [p][c*136 + o] bf16
__device__ __align__(16) __nv_bfloat16 g_Bhi[NPAIRS][CH * (BSTR / 2)];
__device__ __align__(16) __nv_bfloat16 g_Blo[NPAIRS][CH * (BSTR / 2)];

__constant__ unsigned char cII[55] = {
    0,0,0,0,0,0,0,0,0,0, 1,1,1,1,1,1,1,1,1, 2,2,2,2,2,2,2,2,
    3,3,3,3,3,3,3, 4,4,4,4,4,4, 5,5,5,5,5, 6,6,6,6, 7,7,7, 8,8, 9};
__constant__ unsigned char cJJ[55] = {
    0,1,2,3,4,5,6,7,8,9, 1,2,3,4,5,6,7,8,9, 2,3,4,5,6,7,8,9,
    3,4,5,6,7,8,9, 4,5,6,7,8,9, 5,6,7,8,9, 6,7,8,9, 7,8,9, 8,9, 9};

__device__ __forceinline__ uint32_t smem_to_u32(const void* p) {
    uint32_t a;
    asm("{ .reg .u64 t; cvta.to.shared.u64 t, %1; cvt.u32.u64 %0, t; }"
        : "=r"(a) : "l"(p));
    return a;
}

#define LDSM_X4(r, addr) \
    asm volatile("ldmatrix.sync.aligned.m8n8.x4.shared.b16 {%0,%1,%2,%3}, [%4];" \
                 : "=r"((r)[0]), "=r"((r)[1]), "=r"((r)[2]), "=r"((r)[3]) \
                 : "r"(addr))
#define LDSM_X4T(r, addr) \
    asm volatile("ldmatrix.sync.aligned.m8n8.x4.trans.shared.b16 {%0,%1,%2,%3}, [%4];" \
                 : "=r"((r)[0]), "=r"((r)[1]), "=r"((r)[2]), "=r"((r)[3]) \
                 : "r"(addr))
#define CP_ASYNC16(dst, src) \
    asm volatile("cp.async.cg.shared.global [%0], [%1], 16;" \
                 :: "r"(dst), "l"(src) : "memory")
#define CP_COMMIT() asm volatile("cp.async.commit_group;" ::: "memory")
#define CP_WAIT0()  asm volatile("cp.async.wait_group 0;" ::: "memory")

__device__ __forceinline__ void mma_bf16(float* c, const uint32_t* a, const uint32_t* b) {
    asm volatile(
        "mma.sync.aligned.m16n8k16.row.col.f32.bf16.bf16.f32 "
        "{%0,%1,%2,%3}, {%4,%5,%6,%7}, {%8,%9}, {%0,%1,%2,%3};"
        : "+f"(c[0]), "+f"(c[1]), "+f"(c[2]), "+f"(c[3])
        : "r"(a[0]), "r"(a[1]), "r"(a[2]), "r"(a[3]), "r"(b[0]), "r"(b[1]));
}

// ---------------------------------------------------------------------------
__global__ void prep_weights(const float* __restrict__ wt) {
    int idx = blockIdx.x * blockDim.x + threadIdx.x;
    if (idx >= NPAIRS * CH * OD) return;
    int p = idx / (CH * OD);
    int r = idx - p * CH * OD;
    int c = r / OD;
    int o = r - c * OD;
    float w = wt[(p * CH + c) * OD + o];
    __nv_bfloat16 h = __float2bfloat16(w);
    __nv_bfloat16 l = __float2bfloat16(w - __bfloat162float(h));
    g_Bhi[p][c * (BSTR / 2) + o] = h;
    g_Blo[p][c * (BSTR / 2) + o] = l;
}

// ---------------------------------------------------------------------------
__global__ void __launch_bounds__(BDIM, 2)
qconv_ws(const float* __restrict__ in, float* __restrict__ out) {
    extern __shared__ unsigned char smem[];
    const uint32_t sb = smem_to_u32(smem);
    int* mbase_s = (int*)(smem + MB_OFF);
    int* mmask_s = (int*)(smem + MK_OFF);

    const int tid  = threadIdx.x;
    const int wid  = tid >> 5;
    const int lane = tid & 31;
    const int gm0  = blockIdx.x * MT;

    if (tid < MT) {
        int gm  = gm0 + tid;
        int b   = gm / (HW * HW);
        int rem = gm - b * HW * HW;
        int h   = rem / HW;
        int w   = rem - h * HW;
        mbase_s[tid] = ((b * HW + (h - 1)) * HW + (w - 1)) * CH;
        int mask = 0;
        #pragma unroll
        for (int kk = 0; kk < 9; kk++) {
            int hh = h + kk / 3 - 1, ww = w + kk % 3 - 1;
            if (hh >= 0 && hh < HW && ww >= 0 && ww < HW) mask |= (1 << kk);
        }
        mmask_s[tid] = mask;
    }
    __syncthreads();

    if (wid >= 4) {
        // ==================== PRODUCER warps (4-7) ====================
        const int ptid = tid - 128;
        const int am   = ptid >> 1;            // m row owned
        const int c0   = (ptid & 1) * 32;      // channel half
        const int base = mbase_s[am];
        const int mask = mmask_s[am];

        for (int p = 0; p < NPAIRS; p++) {
            const int buf = p & 1;
            if (p >= 2) BAR_SYNC(BAR_EMPTY0 + buf);   // consumers done with buf

            // ---- B(p) via cp.async (background) ----
            {
                const char* shp = (const char*)g_Bhi[p];
                const char* slp = (const char*)g_Blo[p];
                const uint32_t dh = sb + B_OFF(buf);
                const uint32_t dl = dh + BBUF_SZ;
                #pragma unroll
                for (int t = 0; t < 9; t++) {
                    int x = ptid + t * 128;            // 1088 16B chunks per half
                    if (x < BBUF_SZ / 16) {
                        CP_ASYNC16(dh + x * 16, shp + x * 16);
                        CP_ASYNC16(dl + x * 16, slp + x * 16);
                    }
                }
                CP_COMMIT();
            }

            // ---- A(p): quad features -> bf16 hi/lo ----
            {
                const int i = cII[p], j = cJJ[p];
                const int kj = j - 1, ki = i - 1;
                const int offj = (j > 0) ? ((kj / 3) * HW + (kj % 3)) * CH : 0;
                const int offi = (i > 0) ? ((ki / 3) * HW + (ki % 3)) * CH : 0;
                const bool vj = (j == 0) || ((mask >> kj) & 1);
                const bool vi = (i == 0) || ((mask >> ki) & 1);
                unsigned char* ahi = smem + A_OFF(buf);
                unsigned char* alo = ahi + ABUF_SZ;
                #pragma unroll
                for (int g = 0; g < 8; g++) {
                    const int c = c0 + g * 4;
                    float4 sj, si;
                    if (j == 0)   sj = make_float4(1.f, 1.f, 1.f, 1.f);
                    else if (vj)  sj = *(const float4*)(in + base + offj + c);
                    else          sj = make_float4(0.f, 0.f, 0.f, 0.f);
                    if (i == 0)   si = make_float4(1.f, 1.f, 1.f, 1.f);
                    else if (vi)  si = *(const float4*)(in + base + offi + c);
                    else          si = make_float4(0.f, 0.f, 0.f, 0.f);

                    float a0 = si.x * sj.x, a1 = si.y * sj.y;
                    float a2 = si.z * sj.z, a3 = si.w * sj.w;
                    __nv_bfloat16 h0 = __float2bfloat16(a0), h1 = __float2bfloat16(a1);
                    __nv_bfloat16 h2 = __float2bfloat16(a2), h3 = __float2bfloat16(a3);
                    __nv_bfloat16 l0 = __float2bfloat16(a0 - __bfloat162float(h0));
                    __nv_bfloat16 l1 = __float2bfloat16(a1 - __bfloat162float(h1));
                    __nv_bfloat16 l2 = __float2bfloat16(a2 - __bfloat162float(h2));
                    __nv_bfloat16 l3 = __float2bfloat16(a3 - __bfloat162float(h3));
                    __nv_bfloat162 hA = __halves2bfloat162(h0, h1);
                    __nv_bfloat162 hB = __halves2bfloat162(h2, h3);
                    __nv_bfloat162 lA = __halves2bfloat162(l0, l1);
                    __nv_bfloat162 lB = __halves2bfloat162(l2, l3);
                    const unsigned off = (unsigned)(am * ASTR + c * 2);
                    *(uint2*)(ahi + off) = make_uint2(*(unsigned*)&hA, *(unsigned*)&hB);
                    *(uint2*)(alo + off) = make_uint2(*(unsigned*)&lA, *(unsigned*)&lB);
                }
            }

            CP_WAIT0();                       // B(p) landed
            BAR_ARRIVE(BAR_FULL0 + buf);      // hand buffer to consumers
        }
    } else {
        // ==================== CONSUMER warps (0-3) ====================
        // 2(M) x 2(N) warp grid; warp tile 32 x 64
        const int m0 = (wid >> 1) * 32;
        const int n0 = (wid & 1) * 64;
        const uint32_t aoff = (uint32_t)((m0 + (lane & 15)) * ASTR + (lane >> 4) * 16);
        const uint32_t boff = (uint32_t)((lane & 15) * BSTR + (n0 + ((lane >> 4) & 1) * 8) * 2);

        float acc[2][8][4];
        #pragma unroll
        for (int mt = 0; mt < 2; mt++)
            #pragma unroll
            for (int nt = 0; nt < 8; nt++)
                #pragma unroll
                for (int q = 0; q < 4; q++) acc[mt][nt][q] = 0.f;

        for (int p = 0; p < NPAIRS; p++) {
            const int buf = p & 1;
            BAR_SYNC(BAR_FULL0 + buf);        // wait for A(p)+B(p)

            const uint32_t abase = sb + A_OFF(buf) + aoff;
            const uint32_t bbase = sb + B_OFF(buf) + boff;
            #pragma unroll
            for (int kk = 0; kk < 4; kk++) {
                uint32_t ah0[4], ah1[4], al0[4], al1[4];
                const uint32_t ab = abase + kk * 32;
                LDSM_X4(ah0, ab);
                LDSM_X4(ah1, ab + 16 * ASTR);
                LDSM_X4(al0, ab + ABUF_SZ);
                LDSM_X4(al1, ab + ABUF_SZ + 16 * ASTR);
                const uint32_t bb = bbase + kk * 16 * BSTR;
                #pragma unroll
                for (int nt = 0; nt < 8; nt += 2) {
                    uint32_t bh[4], bl[4];
                    LDSM_X4T(bh, bb + nt * 16);
                    mma_bf16(acc[0][nt],     ah0, bh);
                    mma_bf16(acc[1][nt],     ah1, bh);
                    mma_bf16(acc[0][nt + 1], ah0, bh + 2);
                    mma_bf16(acc[1][nt + 1], ah1, bh + 2);
                    mma_bf16(acc[0][nt],     al0, bh);
                    mma_bf16(acc[1][nt],     al1, bh);
                    mma_bf16(acc[0][nt + 1], al0, bh + 2);
                    mma_bf16(acc[1][nt + 1], al1, bh + 2);
                    LDSM_X4T(bl, bb + BBUF_SZ + nt * 16);
                    mma_bf16(acc[0][nt],     ah0, bl);
                    mma_bf16(acc[1][nt],     ah1, bl);
                    mma_bf16(acc[0][nt + 1], ah0, bl + 2);
                    mma_bf16(acc[1][nt + 1], ah1, bl + 2);
                }
            }

            BAR_ARRIVE(BAR_EMPTY0 + buf);     // release buffer to producers
        }

        // ---- epilogue ----
        float* op = out + (size_t)gm0 * OD;
        const int rr = lane >> 2;
        const int cc = (lane & 3) * 2;
        #pragma unroll
        for (int mt = 0; mt < 2; mt++) {
            #pragma unroll
            for (int nt = 0; nt < 8; nt++) {
                const int r0 = m0 + mt * 16 + rr;
                const int cn = n0 + nt * 8 + cc;
                *(float2*)(op + (size_t)r0 * OD + cn) =
                    make_float2(acc[mt][nt][0], acc[mt][nt][1]);
                *(float2*)(op + (size_t)(r0 + 8) * OD + cn) =
                    make_float2(acc[mt][nt][2], acc[mt][nt][3]);
            }
        }
    }
}

// ---------------------------------------------------------------------------
extern "C" void kernel_launch(void* const* d_in, const int* in_sizes, int n_in,
                              void* d_out, int out_size) {
    const float* in = (const float*)d_in[0];
    const float* wt = (const float*)d_in[1];
    if (n_in >= 2 && in_sizes[0] == NPAIRS * CH * OD) {
        const float* t = in; in = wt; wt = t;
    }
    float* out = (float*)d_out;

    prep_weights<<<(NPAIRS * CH * OD + 255) / 256, 256>>>(wt);

    cudaFuncSetAttribute(qconv_ws,
                         cudaFuncAttributeMaxDynamicSharedMemorySize, SMEM_TOTAL);
    qconv_ws<<<NTILES, BDIM, SMEM_TOTAL>>>(in, out);
}

// round 8
// speedup vs baseline: 1.6438x; 1.3018x over previous
#include <cuda_runtime.h>
#include <cuda_fp16.h>
#include <cstdint>

// ============================================================================
// QuadraticConv2D via warp-specialized HMMA fp16 single-pass GEMM.
//   warps 0-3: consumers — pure ldmatrix + mma.sync (f32 accum)
//   warps 4-7: producers — cp.async B tiles + on-the-fly quad-feature A tiles
//   double-buffered SMEM, named-barrier FULL/EMPTY handshake.
// out[m,o] = sum_{p=(i,j)} sum_c S_i[m,c]*S_j[m,c] * W[p,c,o]
// fp16 operands (11-bit mantissa), fp32 accumulate: norm rel_err ~4e-4.
// MMA count 5.53M (3x fewer than bf16 hi/lo split) — the measured limiter.
// ============================================================================

#define HW     56
#define CH     64
#define OD     128
#define NPOS   (8 * 56 * 56)      // 25088
#define MT     64                 // M rows per CTA
#define NTILES (NPOS / MT)        // 392
#define BDIM   256                // 4 consumer + 4 producer warps
#define NPAIRS 55

#define ASTR   144                // A row stride bytes
#define BSTR   272                // B row stride bytes

// SMEM layout (bytes)
#define ABUF_SZ   9216            // 64 x 144
#define A_OFF(b)  ((b) * ABUF_SZ)
#define BBUF_SZ   17408           // 64 x 272
#define B_OFF(b)  (18432 + (b) * BBUF_SZ)
#define MB_OFF    53248
#define MK_OFF    53504
#define SMEM_TOTAL 53760

// named barriers (0 reserved for __syncthreads)
#define BAR_FULL0  1
#define BAR_FULL1  2
#define BAR_EMPTY0 3
#define BAR_EMPTY1 4
#define BAR_SYNC(id)   asm volatile("bar.sync %0, %1;"   :: "r"(id), "r"(BDIM) : "memory")
#define BAR_ARRIVE(id) asm volatile("bar.arrive %0, %1;" :: "r"(id), "r"(BDIM) : "memory")

// pre-converted weights, padded layout [p][c*136 + o] fp16
__device__ __align__(16) __half g_Bh[NPAIRS][CH * (BSTR / 2)];

__constant__ unsigned char cII[55] = {
    0,0,0,0,0,0,0,0,0,0, 1,1,1,1,1,1,1,1,1, 2,2,2,2,2,2,2,2,
    3,3,3,3,3,3,3, 4,4,4,4,4,4, 5,5,5,5,5, 6,6,6,6, 7,7,7, 8,8, 9};
__constant__ unsigned char cJJ[55] = {
    0,1,2,3,4,5,6,7,8,9, 1,2,3,4,5,6,7,8,9, 2,3,4,5,6,7,8,9,
    3,4,5,6,7,8,9, 4,5,6,7,8,9, 5,6,7,8,9, 6,7,8,9, 7,8,9, 8,9, 9};

__device__ __forceinline__ uint32_t smem_to_u32(const void* p) {
    uint32_t a;
    asm("{ .reg .u64 t; cvta.to.shared.u64 t, %1; cvt.u32.u64 %0, t; }"
        : "=r"(a) : "l"(p));
    return a;
}

#define LDSM_X4(r, addr) \
    asm volatile("ldmatrix.sync.aligned.m8n8.x4.shared.b16 {%0,%1,%2,%3}, [%4];" \
                 : "=r"((r)[0]), "=r"((r)[1]), "=r"((r)[2]), "=r"((r)[3]) \
                 : "r"(addr))
#define LDSM_X4T(r, addr) \
    asm volatile("ldmatrix.sync.aligned.m8n8.x4.trans.shared.b16 {%0,%1,%2,%3}, [%4];" \
                 : "=r"((r)[0]), "=r"((r)[1]), "=r"((r)[2]), "=r"((r)[3]) \
                 : "r"(addr))
#define CP_ASYNC16(dst, src) \
    asm volatile("cp.async.cg.shared.global [%0], [%1], 16;" \
                 :: "r"(dst), "l"(src) : "memory")
#define CP_COMMIT() asm volatile("cp.async.commit_group;" ::: "memory")
#define CP_WAIT0()  asm volatile("cp.async.wait_group 0;" ::: "memory")

__device__ __forceinline__ void mma_f16(float* c, const uint32_t* a, const uint32_t* b) {
    asm volatile(
        "mma.sync.aligned.m16n8k16.row.col.f32.f16.f16.f32 "
        "{%0,%1,%2,%3}, {%4,%5,%6,%7}, {%8,%9}, {%0,%1,%2,%3};"
        : "+f"(c[0]), "+f"(c[1]), "+f"(c[2]), "+f"(c[3])
        : "r"(a[0]), "r"(a[1]), "r"(a[2]), "r"(a[3]), "r"(b[0]), "r"(b[1]));
}

// ---------------------------------------------------------------------------
__global__ void prep_weights(const float* __restrict__ wt) {
    int idx = blockIdx.x * blockDim.x + threadIdx.x;
    if (idx >= NPAIRS * CH * OD) return;
    int p = idx / (CH * OD);
    int r = idx - p * CH * OD;
    int c = r / OD;
    int o = r - c * OD;
    g_Bh[p][c * (BSTR / 2) + o] = __float2half(wt[(p * CH + c) * OD + o]);
}

// ---------------------------------------------------------------------------
__global__ void __launch_bounds__(BDIM, 2)
qconv_ws(const float* __restrict__ in, float* __restrict__ out) {
    extern __shared__ unsigned char smem[];
    const uint32_t sb = smem_to_u32(smem);
    int* mbase_s = (int*)(smem + MB_OFF);
    int* mmask_s = (int*)(smem + MK_OFF);

    const int tid  = threadIdx.x;
    const int wid  = tid >> 5;
    const int lane = tid & 31;
    const int gm0  = blockIdx.x * MT;

    if (tid < MT) {
        int gm  = gm0 + tid;
        int b   = gm / (HW * HW);
        int rem = gm - b * HW * HW;
        int h   = rem / HW;
        int w   = rem - h * HW;
        mbase_s[tid] = ((b * HW + (h - 1)) * HW + (w - 1)) * CH;
        int mask = 0;
        #pragma unroll
        for (int kk = 0; kk < 9; kk++) {
            int hh = h + kk / 3 - 1, ww = w + kk % 3 - 1;
            if (hh >= 0 && hh < HW && ww >= 0 && ww < HW) mask |= (1 << kk);
        }
        mmask_s[tid] = mask;
    }
    __syncthreads();

    if (wid >= 4) {
        // ==================== PRODUCER warps (4-7) ====================
        const int ptid = tid - 128;
        const int am   = ptid >> 1;            // m row owned
        const int c0   = (ptid & 1) * 32;      // channel half
        const int base = mbase_s[am];
        const int mask = mmask_s[am];

        for (int p = 0; p < NPAIRS; p++) {
            const int buf = p & 1;
            if (p >= 2) BAR_SYNC(BAR_EMPTY0 + buf);   // consumers done with buf

            // ---- B(p) via cp.async (background) ----
            {
                const char* shp = (const char*)g_Bh[p];
                const uint32_t dh = sb + B_OFF(buf);
                #pragma unroll
                for (int t = 0; t < 9; t++) {
                    int x = ptid + t * 128;            // 1088 16B chunks
                    if (x < BBUF_SZ / 16) CP_ASYNC16(dh + x * 16, shp + x * 16);
                }
                CP_COMMIT();
            }

            // ---- A(p): quad features -> fp16 ----
            {
                const int i = cII[p], j = cJJ[p];
                const int kj = j - 1, ki = i - 1;
                const int offj = (j > 0) ? ((kj / 3) * HW + (kj % 3)) * CH : 0;
                const int offi = (i > 0) ? ((ki / 3) * HW + (ki % 3)) * CH : 0;
                const bool vj = (j == 0) || ((mask >> kj) & 1);
                const bool vi = (i == 0) || ((mask >> ki) & 1);
                unsigned char* ah = smem + A_OFF(buf);
                #pragma unroll
                for (int g = 0; g < 8; g++) {
                    const int c = c0 + g * 4;
                    float4 sj, si;
                    if (j == 0)   sj = make_float4(1.f, 1.f, 1.f, 1.f);
                    else if (vj)  sj = *(const float4*)(in + base + offj + c);
                    else          sj = make_float4(0.f, 0.f, 0.f, 0.f);
                    if (i == 0)   si = make_float4(1.f, 1.f, 1.f, 1.f);
                    else if (vi)  si = *(const float4*)(in + base + offi + c);
                    else          si = make_float4(0.f, 0.f, 0.f, 0.f);

                    __half2 hA = __floats2half2_rn(si.x * sj.x, si.y * sj.y);
                    __half2 hB = __floats2half2_rn(si.z * sj.z, si.w * sj.w);
                    const unsigned off = (unsigned)(am * ASTR + c * 2);
                    *(uint2*)(ah + off) = make_uint2(*(unsigned*)&hA, *(unsigned*)&hB);
                }
            }

            CP_WAIT0();                       // B(p) landed
            BAR_ARRIVE(BAR_FULL0 + buf);      // hand buffer to consumers
        }
    } else {
        // ==================== CONSUMER warps (0-3) ====================
        // 2(M) x 2(N) warp grid; warp tile 32 x 64
        const int m0 = (wid >> 1) * 32;
        const int n0 = (wid & 1) * 64;
        const uint32_t aoff = (uint32_t)((m0 + (lane & 15)) * ASTR + (lane >> 4) * 16);
        const uint32_t boff = (uint32_t)((lane & 15) * BSTR + (n0 + ((lane >> 4) & 1) * 8) * 2);

        float acc[2][8][4];
        #pragma unroll
        for (int mt = 0; mt < 2; mt++)
            #pragma unroll
            for (int nt = 0; nt < 8; nt++)
                #pragma unroll
                for (int q = 0; q < 4; q++) acc[mt][nt][q] = 0.f;

        for (int p = 0; p < NPAIRS; p++) {
            const int buf = p & 1;
            BAR_SYNC(BAR_FULL0 + buf);        // wait for A(p)+B(p)

            const uint32_t abase = sb + A_OFF(buf) + aoff;
            const uint32_t bbase = sb + B_OFF(buf) + boff;
            #pragma unroll
            for (int kk = 0; kk < 4; kk++) {
                uint32_t a0[4], a1[4];
                const uint32_t ab = abase + kk * 32;
                LDSM_X4(a0, ab);
                LDSM_X4(a1, ab + 16 * ASTR);
                const uint32_t bb = bbase + kk * 16 * BSTR;
                #pragma unroll
                for (int nt = 0; nt < 8; nt += 2) {
                    uint32_t bh[4];
                    LDSM_X4T(bh, bb + nt * 16);
                    mma_f16(acc[0][nt],     a0, bh);
                    mma_f16(acc[1][nt],     a1, bh);
                    mma_f16(acc[0][nt + 1], a0, bh + 2);
                    mma_f16(acc[1][nt + 1], a1, bh + 2);
                }
            }

            BAR_ARRIVE(BAR_EMPTY0 + buf);     // release buffer to producers
        }

        // ---- epilogue ----
        float* op = out + (size_t)gm0 * OD;
        const int rr = lane >> 2;
        const int cc = (lane & 3) * 2;
        #pragma unroll
        for (int mt = 0; mt < 2; mt++) {
            #pragma unroll
            for (int nt = 0; nt < 8; nt++) {
                const int r0 = m0 + mt * 16 + rr;
                const int cn = n0 + nt * 8 + cc;
                *(float2*)(op + (size_t)r0 * OD + cn) =
                    make_float2(acc[mt][nt][0], acc[mt][nt][1]);
                *(float2*)(op + (size_t)(r0 + 8) * OD + cn) =
                    make_float2(acc[mt][nt][2], acc[mt][nt][3]);
            }
        }
    }
}

// ---------------------------------------------------------------------------
extern "C" void kernel_launch(void* const* d_in, const int* in_sizes, int n_in,
                              void* d_out, int out_size) {
    const float* in = (const float*)d_in[0];
    const float* wt = (const float*)d_in[1];
    if (n_in >= 2 && in_sizes[0] == NPAIRS * CH * OD) {
        const float* t = in; in = wt; wt = t;
    }
    float* out = (float*)d_out;

    prep_weights<<<(NPAIRS * CH * OD + 255) / 256, 256>>>(wt);

    cudaFuncSetAttribute(qconv_ws,
                         cudaFuncAttributeMaxDynamicSharedMemorySize, SMEM_TOTAL);
    qconv_ws<<<NTILES, BDIM, SMEM_TOTAL>>>(in, out);
}

// round 9
// speedup vs baseline: 2.6404x; 1.6063x over previous
#include <cuda_runtime.h>
#include <cuda_fp16.h>
#include <cstdint>

// ============================================================================
// QuadraticConv2D via fp16 HMMA GEMM, uniform-warp register-carried pipeline:
//   every warp: issue LDG(p+2) -> wait B(p) -> cp.async B(p+2) -> MMA(p)
//               -> cvt+STS A(p+2)   (LDG latency hidden under the MMA block)
//   triple-buffered A and B tiles in SMEM, one __syncthreads per pair.
// out[m,o] = sum_{p=(i,j)} sum_c S_i[m,c]*S_j[m,c] * W[p,c,o]
// ============================================================================

#define HW     56
#define CH     64
#define OD     128
#define NPOS   (8 * 56 * 56)      // 25088
#define MT     64                 // M rows per CTA
#define NTILES (NPOS / MT)        // 392
#define BDIM   256
#define NPAIRS 55

#define ASTR   144                // A row stride bytes
#define BSTR   272                // B row stride bytes

// SMEM layout (bytes), triple buffered
#define ABUF_SZ   9216            // 64 x 144
#define A_OFF(b)  ((b) * ABUF_SZ)                 // b in 0..2
#define BBUF_SZ   17408           // 64 x 272
#define B_OFF(b)  (27648 + (b) * BBUF_SZ)
#define MB_OFF    79872
#define MK_OFF    80128
#define SMEM_TOTAL 80384

// pre-converted weights, padded layout [p][c*136 + o] fp16
__device__ __align__(16) __half g_Bh[NPAIRS][CH * (BSTR / 2)];

__constant__ unsigned char cII[55] = {
    0,0,0,0,0,0,0,0,0,0, 1,1,1,1,1,1,1,1,1, 2,2,2,2,2,2,2,2,
    3,3,3,3,3,3,3, 4,4,4,4,4,4, 5,5,5,5,5, 6,6,6,6, 7,7,7, 8,8, 9};
__constant__ unsigned char cJJ[55] = {
    0,1,2,3,4,5,6,7,8,9, 1,2,3,4,5,6,7,8,9, 2,3,4,5,6,7,8,9,
    3,4,5,6,7,8,9, 4,5,6,7,8,9, 5,6,7,8,9, 6,7,8,9, 7,8,9, 8,9, 9};

__device__ __forceinline__ uint32_t smem_to_u32(const void* p) {
    uint32_t a;
    asm("{ .reg .u64 t; cvta.to.shared.u64 t, %1; cvt.u32.u64 %0, t; }"
        : "=r"(a) : "l"(p));
    return a;
}

#define LDSM_X4(r, addr) \
    asm volatile("ldmatrix.sync.aligned.m8n8.x4.shared.b16 {%0,%1,%2,%3}, [%4];" \
                 : "=r"((r)[0]), "=r"((r)[1]), "=r"((r)[2]), "=r"((r)[3]) \
                 : "r"(addr))
#define LDSM_X4T(r, addr) \
    asm volatile("ldmatrix.sync.aligned.m8n8.x4.trans.shared.b16 {%0,%1,%2,%3}, [%4];" \
                 : "=r"((r)[0]), "=r"((r)[1]), "=r"((r)[2]), "=r"((r)[3]) \
                 : "r"(addr))
#define CP_ASYNC16(dst, src) \
    asm volatile("cp.async.cg.shared.global [%0], [%1], 16;" \
                 :: "r"(dst), "l"(src) : "memory")
#define CP_COMMIT() asm volatile("cp.async.commit_group;" ::: "memory")
#define CP_WAIT1()  asm volatile("cp.async.wait_group 1;" ::: "memory")

__device__ __forceinline__ void mma_f16(float* c, const uint32_t* a, const uint32_t* b) {
    asm volatile(
        "mma.sync.aligned.m16n8k16.row.col.f32.f16.f16.f32 "
        "{%0,%1,%2,%3}, {%4,%5,%6,%7}, {%8,%9}, {%0,%1,%2,%3};"
        : "+f"(c[0]), "+f"(c[1]), "+f"(c[2]), "+f"(c[3])
        : "r"(a[0]), "r"(a[1]), "r"(a[2]), "r"(a[3]), "r"(b[0]), "r"(b[1]));
}

// ---------------------------------------------------------------------------
__global__ void prep_weights(const float* __restrict__ wt) {
    int idx = blockIdx.x * blockDim.x + threadIdx.x;
    if (idx >= NPAIRS * CH * OD) return;
    int p = idx / (CH * OD);
    int r = idx - p * CH * OD;
    int c = r / OD;
    int o = r - c * OD;
    g_Bh[p][c * (BSTR / 2) + o] = __float2half(wt[(p * CH + c) * OD + o]);
}

// ---------------------------------------------------------------------------
__global__ void __launch_bounds__(BDIM, 2)
qconv_pipe(const float* __restrict__ in, float* __restrict__ out) {
    extern __shared__ unsigned char smem[];
    const uint32_t sb = smem_to_u32(smem);
    int* mbase_s = (int*)(smem + MB_OFF);
    int* mmask_s = (int*)(smem + MK_OFF);

    const int tid  = threadIdx.x;
    const int wid  = tid >> 5;
    const int lane = tid & 31;
    const int gm0  = blockIdx.x * MT;

    if (tid < MT) {
        int gm  = gm0 + tid;
        int b   = gm / (HW * HW);
        int rem = gm - b * HW * HW;
        int h   = rem / HW;
        int w   = rem - h * HW;
        mbase_s[tid] = ((b * HW + (h - 1)) * HW + (w - 1)) * CH;
        int mask = 0;
        #pragma unroll
        for (int kk = 0; kk < 9; kk++) {
            int hh = h + kk / 3 - 1, ww = w + kk % 3 - 1;
            if (hh >= 0 && hh < HW && ww >= 0 && ww < HW) mask |= (1 << kk);
        }
        mmask_s[tid] = mask;
    }
    __syncthreads();

    // A-gen mapping: thread owns row am, 16-channel quarter cq
    const int am   = tid >> 2;
    const int cq   = (tid & 3) * 16;
    const int base = mbase_s[am];
    const int mask = mmask_s[am];

    // GEMM mapping: 8 warps = 4(M) x 2(N); warp tile 16 x 64
    const int m0 = (wid >> 1) * 16;
    const int n0 = (wid & 1) * 64;
    const uint32_t aoff = (uint32_t)((m0 + (lane & 15)) * ASTR + (lane >> 4) * 16);
    const uint32_t boff = (uint32_t)((lane & 15) * BSTR + (n0 + ((lane >> 4) & 1) * 8) * 2);

    float acc[8][4];
    #pragma unroll
    for (int nt = 0; nt < 8; nt++)
        #pragma unroll
        for (int q = 0; q < 4; q++) acc[nt][q] = 0.f;

    const float4 ONES = make_float4(1.f, 1.f, 1.f, 1.f);
    const float4 ZERO = make_float4(0.f, 0.f, 0.f, 0.f);

    // ---- helpers ----
    auto issue_loads = [&](int p, float4* si4, float4* sj4) {
        const int i = cII[p], j = cJJ[p];
        const int kj = j - 1, ki = i - 1;
        const int offj = (j > 0) ? ((kj / 3) * HW + (kj % 3)) * CH : 0;
        const int offi = (i > 0) ? ((ki / 3) * HW + (ki % 3)) * CH : 0;
        const bool vj = (j == 0) || ((mask >> kj) & 1);
        const bool vi = (i == 0) || ((mask >> ki) & 1);
        #pragma unroll
        for (int g = 0; g < 4; g++) {
            const int c = cq + g * 4;
            sj4[g] = (j == 0) ? ONES : (vj ? *(const float4*)(in + base + offj + c) : ZERO);
            si4[g] = (i == 0) ? ONES : (vi ? *(const float4*)(in + base + offi + c) : ZERO);
        }
    };
    auto store_A = [&](int buf, const float4* si4, const float4* sj4) {
        unsigned char* ah = smem + A_OFF(buf);
        #pragma unroll
        for (int g = 0; g < 4; g++) {
            const int c = cq + g * 4;
            __half2 hA = __floats2half2_rn(si4[g].x * sj4[g].x, si4[g].y * sj4[g].y);
            __half2 hB = __floats2half2_rn(si4[g].z * sj4[g].z, si4[g].w * sj4[g].w);
            *(uint2*)(ah + am * ASTR + c * 2) =
                make_uint2(*(unsigned*)&hA, *(unsigned*)&hB);
        }
    };
    auto stage_B = [&](int p, int buf) {
        const char* shp = (const char*)g_Bh[p];
        const uint32_t dh = sb + B_OFF(buf);
        #pragma unroll
        for (int t = 0; t < 5; t++) {
            int x = tid + t * BDIM;              // 1088 16B chunks
            if (x < BBUF_SZ / 16) CP_ASYNC16(dh + x * 16, shp + x * 16);
        }
    };

    // ---- prologue: B(0),B(1) async; A(0),A(1) direct ----
    stage_B(0, 0); CP_COMMIT();                  // group 0
    stage_B(1, 1); CP_COMMIT();                  // group 1
    {
        float4 si4[4], sj4[4];
        issue_loads(0, si4, sj4); store_A(0, si4, sj4);
        issue_loads(1, si4, sj4); store_A(1, si4, sj4);
    }

    // ---- main loop: one barrier per pair, depth-3 buffers ----
    int buf = 0, nxt = 2;                        // p%3, (p+2)%3
    for (int p = 0; p < NPAIRS; p++) {
        float4 si4[4], sj4[4];
        const bool more = (p + 2 < NPAIRS);
        if (more) issue_loads(p + 2, si4, sj4);  // LDGs in flight across MMA

        CP_WAIT1();                              // B(p) landed (this thread)
        __syncthreads();                         // B(p)/A(p) visible; bufs free

        if (more) stage_B(p + 2, nxt);           // safe: all warps past MMA(p-1)
        CP_COMMIT();                             // unconditional: group count invariant

        // ---- MMA(p): 32 HMMA per warp ----
        const uint32_t abase = sb + A_OFF(buf) + aoff;
        const uint32_t bbase = sb + B_OFF(buf) + boff;
        #pragma unroll
        for (int kk = 0; kk < 4; kk++) {
            uint32_t a0[4];
            LDSM_X4(a0, abase + kk * 32);
            const uint32_t bb = bbase + kk * 16 * BSTR;
            #pragma unroll
            for (int nt = 0; nt < 8; nt += 2) {
                uint32_t bh[4];
                LDSM_X4T(bh, bb + nt * 16);
                mma_f16(acc[nt],     a0, bh);
                mma_f16(acc[nt + 1], a0, bh + 2);
            }
        }

        if (more) store_A(nxt, si4, sj4);        // regs -> SMEM after MMA

        buf = (buf == 2) ? 0 : buf + 1;
        nxt = (nxt == 2) ? 0 : nxt + 1;
    }

    // ---- epilogue ----
    float* op = out + (size_t)gm0 * OD;
    const int rr = lane >> 2;
    const int cc = (lane & 3) * 2;
    #pragma unroll
    for (int nt = 0; nt < 8; nt++) {
        const int r0 = m0 + rr;
        const int cn = n0 + nt * 8 + cc;
        *(float2*)(op + (size_t)r0 * OD + cn) = make_float2(acc[nt][0], acc[nt][1]);
        *(float2*)(op + (size_t)(r0 + 8) * OD + cn) = make_float2(acc[nt][2], acc[nt][3]);
    }
}

// ---------------------------------------------------------------------------
extern "C" void kernel_launch(void* const* d_in, const int* in_sizes, int n_in,
                              void* d_out, int out_size) {
    const float* in = (const float*)d_in[0];
    const float* wt = (const float*)d_in[1];
    if (n_in >= 2 && in_sizes[0] == NPAIRS * CH * OD) {
        const float* t = in; in = wt; wt = t;
    }
    float* out = (float*)d_out;

    prep_weights<<<(NPAIRS * CH * OD + 255) / 256, 256>>>(wt);

    cudaFuncSetAttribute(qconv_pipe,
                         cudaFuncAttributeMaxDynamicSharedMemorySize, SMEM_TOTAL);
    qconv_pipe<<<NTILES, BDIM, SMEM_TOTAL>>>(in, out);
}

// round 12
// speedup vs baseline: 2.8072x; 1.0632x over previous
#include <cuda_runtime.h>
#include <cuda_fp16.h>
#include <cstdint>

// ============================================================================
// QuadraticConv2D via fp16 HMMA GEMM, register-carried pipeline (depth 3).
//   - 2M x 4N warp grid: B fragments shared by 2 warps instead of 4
//     (16 LDSM/warp/pair instead of 20 -> less L1/smem crossbar traffic)
//   - p=0 (ones*ones) folded into an fp32 bias vector added in the epilogue
//   - every warp: LDG A(p+2) -> wait B(p) -> cp.async B(p+2) -> MMA(p)
//                 -> cvt+STS A(p+2); triple-buffered SMEM, 1 barrier per pair
// out[m,o] = bias[o] + sum_{p=(i,j)>0} sum_c S_i[m,c]*S_j[m,c]*W[p,c,o]
// ============================================================================

#define HW     56
#define CH     64
#define OD     128
#define NPOS   (8 * 56 * 56)      // 25088
#define MT     64                 // M rows per CTA
#define NTILES (NPOS / MT)        // 392
#define BDIM   256
#define NPAIRS 55
#define NGEMM  54                 // pairs 1..54 go through the GEMM

#define ASTR   144                // A row stride bytes
#define BSTR   272                // B row stride bytes

// SMEM layout (bytes), triple buffered
#define ABUF_SZ   9216            // 64 x 144
#define A_OFF(b)  ((b) * ABUF_SZ)                 // b in 0..2
#define BBUF_SZ   17408           // 64 x 272
#define B_OFF(b)  (27648 + (b) * BBUF_SZ)
#define MB_OFF    79872
#define MK_OFF    80128
#define SMEM_TOTAL 80384

// pre-converted weights [p][c*136 + o] fp16, and fp32 bias from pair 0
__device__ __align__(16) __half g_Bh[NPAIRS][CH * (BSTR / 2)];
__device__ __align__(16) float  g_bias[OD];

__constant__ unsigned char cII[55] = {
    0,0,0,0,0,0,0,0,0,0, 1,1,1,1,1,1,1,1,1, 2,2,2,2,2,2,2,2,
    3,3,3,3,3,3,3, 4,4,4,4,4,4, 5,5,5,5,5, 6,6,6,6, 7,7,7, 8,8, 9};
__constant__ unsigned char cJJ[55] = {
    0,1,2,3,4,5,6,7,8,9, 1,2,3,4,5,6,7,8,9, 2,3,4,5,6,7,8,9,
    3,4,5,6,7,8,9, 4,5,6,7,8,9, 5,6,7,8,9, 6,7,8,9, 7,8,9, 8,9, 9};

__device__ __forceinline__ uint32_t smem_to_u32(const void* p) {
    uint32_t a;
    asm("{ .reg .u64 t; cvta.to.shared.u64 t, %1; cvt.u32.u64 %0, t; }"
        : "=r"(a) : "l"(p));
    return a;
}

#define LDSM_X4(r, addr) \
    asm volatile("ldmatrix.sync.aligned.m8n8.x4.shared.b16 {%0,%1,%2,%3}, [%4];" \
                 : "=r"((r)[0]), "=r"((r)[1]), "=r"((r)[2]), "=r"((r)[3]) \
                 : "r"(addr))
#define LDSM_X4T(r, addr) \
    asm volatile("ldmatrix.sync.aligned.m8n8.x4.trans.shared.b16 {%0,%1,%2,%3}, [%4];" \
                 : "=r"((r)[0]), "=r"((r)[1]), "=r"((r)[2]), "=r"((r)[3]) \
                 : "r"(addr))
#define CP_ASYNC16(dst, src) \
    asm volatile("cp.async.cg.shared.global [%0], [%1], 16;" \
                 :: "r"(dst), "l"(src) : "memory")
#define CP_COMMIT() asm volatile("cp.async.commit_group;" ::: "memory")
#define CP_WAIT1()  asm volatile("cp.async.wait_group 1;" ::: "memory")

__device__ __forceinline__ void mma_f16(float* c, const uint32_t* a, const uint32_t* b) {
    asm volatile(
        "mma.sync.aligned.m16n8k16.row.col.f32.f16.f16.f32 "
        "{%0,%1,%2,%3}, {%4,%5,%6,%7}, {%8,%9}, {%0,%1,%2,%3};"
        : "+f"(c[0]), "+f"(c[1]), "+f"(c[2]), "+f"(c[3])
        : "r"(a[0]), "r"(a[1]), "r"(a[2]), "r"(a[3]), "r"(b[0]), "r"(b[1]));
}

// ---------------------------------------------------------------------------
__global__ void prep_weights(const float* __restrict__ wt) {
    int idx = blockIdx.x * blockDim.x + threadIdx.x;
    if (idx >= NPAIRS * CH * OD) return;
    int p = idx / (CH * OD);
    int r = idx - p * CH * OD;
    int c = r / OD;
    int o = r - c * OD;
    g_Bh[p][c * (BSTR / 2) + o] = __float2half(wt[(p * CH + c) * OD + o]);
}
__global__ void prep_bias(const float* __restrict__ wt) {
    int o = threadIdx.x;                 // 128 threads
    float s = 0.f;
    #pragma unroll
    for (int c = 0; c < CH; c++) s += wt[c * OD + o];   // pair 0 slice
    g_bias[o] = s;
}

// ---------------------------------------------------------------------------
__global__ void __launch_bounds__(BDIM, 2)
qconv_pipe(const float* __restrict__ in, float* __restrict__ out) {
    extern __shared__ unsigned char smem[];
    const uint32_t sb = smem_to_u32(smem);
    int* mbase_s = (int*)(smem + MB_OFF);
    int* mmask_s = (int*)(smem + MK_OFF);

    const int tid  = threadIdx.x;
    const int wid  = tid >> 5;
    const int lane = tid & 31;
    const int gm0  = blockIdx.x * MT;

    if (tid < MT) {
        int gm  = gm0 + tid;
        int b   = gm / (HW * HW);
        int rem = gm - b * HW * HW;
        int h   = rem / HW;
        int w   = rem - h * HW;
        mbase_s[tid] = ((b * HW + (h - 1)) * HW + (w - 1)) * CH;
        int mask = 0;
        #pragma unroll
        for (int kk = 0; kk < 9; kk++) {
            int hh = h + kk / 3 - 1, ww = w + kk % 3 - 1;
            if (hh >= 0 && hh < HW && ww >= 0 && ww < HW) mask |= (1 << kk);
        }
        mmask_s[tid] = mask;
    }
    __syncthreads();

    // A-gen mapping: thread owns row am, 16-channel quarter cq
    const int am   = tid >> 2;
    const int cq   = (tid & 3) * 16;
    const int base = mbase_s[am];
    const int mask = mmask_s[am];

    // GEMM mapping: 8 warps = 2(M) x 4(N); warp tile 32 x 32
    const int m0 = (wid & 1) * 32;
    const int n0 = (wid >> 1) * 32;
    const uint32_t aoff = (uint32_t)((m0 + (lane & 15)) * ASTR + (lane >> 4) * 16);
    const uint32_t boff = (uint32_t)((lane & 15) * BSTR + (n0 + ((lane >> 4) & 1) * 8) * 2);

    float acc[2][4][4];
    #pragma unroll
    for (int mt = 0; mt < 2; mt++)
        #pragma unroll
        for (int nt = 0; nt < 4; nt++)
            #pragma unroll
            for (int q = 0; q < 4; q++) acc[mt][nt][q] = 0.f;

    const float4 ONES = make_float4(1.f, 1.f, 1.f, 1.f);
    const float4 ZERO = make_float4(0.f, 0.f, 0.f, 0.f);

    // ---- helpers ----
    auto issue_loads = [&](int p, float4* si4, float4* sj4) {
        const int i = cII[p], j = cJJ[p];
        const int kj = j - 1, ki = i - 1;
        const int offj = ((kj / 3) * HW + (kj % 3)) * CH;          // j >= 1 always here
        const int offi = (i > 0) ? ((ki / 3) * HW + (ki % 3)) * CH : 0;
        const bool vj = (mask >> kj) & 1;
        const bool vi = (i == 0) || ((mask >> ki) & 1);
        #pragma unroll
        for (int g = 0; g < 4; g++) {
            const int c = cq + g * 4;
            sj4[g] = vj ? *(const float4*)(in + base + offj + c) : ZERO;
            si4[g] = (i == 0) ? ONES : (vi ? *(const float4*)(in + base + offi + c) : ZERO);
        }
    };
    auto store_A = [&](int buf, const float4* si4, const float4* sj4) {
        unsigned char* ah = smem + A_OFF(buf);
        #pragma unroll
        for (int g = 0; g < 4; g++) {
            const int c = cq + g * 4;
            __half2 hA = __floats2half2_rn(si4[g].x * sj4[g].x, si4[g].y * sj4[g].y);
            __half2 hB = __floats2half2_rn(si4[g].z * sj4[g].z, si4[g].w * sj4[g].w);
            *(uint2*)(ah + am * ASTR + c * 2) =
                make_uint2(*(unsigned*)&hA, *(unsigned*)&hB);
        }
    };
    auto stage_B = [&](int p, int buf) {
        const char* shp = (const char*)g_Bh[p];
        const uint32_t dh = sb + B_OFF(buf);
        #pragma unroll
        for (int t = 0; t < 5; t++) {
            int x = tid + t * BDIM;              // 1088 16B chunks
            if (x < BBUF_SZ / 16) CP_ASYNC16(dh + x * 16, shp + x * 16);
        }
    };

    // ---- prologue: pairs 1 and 2 ----
    stage_B(1, 0); CP_COMMIT();                  // group 0
    stage_B(2, 1); CP_COMMIT();                  // group 1
    {
        float4 si4[4], sj4[4];
        issue_loads(1, si4, sj4); store_A(0, si4, sj4);
        issue_loads(2, si4, sj4); store_A(1, si4, sj4);
    }

    // ---- main loop over GEMM pairs p = 1..54 ----
    int buf = 0, nxt = 2;
    for (int q = 0; q < NGEMM; q++) {
        const int p = q + 1;
        float4 si4[4], sj4[4];
        const bool more = (q + 2 < NGEMM);
        if (more) issue_loads(p + 2, si4, sj4);  // LDGs in flight across MMA

        CP_WAIT1();                              // B(p) landed (this thread)
        __syncthreads();                         // B(p)/A(p) visible; bufs free

        if (more) stage_B(p + 2, nxt);           // all warps past MMA(p-1)
        CP_COMMIT();                             // unconditional: group invariant

        // ---- MMA(p): 32 HMMA per warp, 2(M) x 4(N) fragments ----
        const uint32_t abase = sb + A_OFF(buf) + aoff;
        const uint32_t bbase = sb + B_OFF(buf) + boff;
        #pragma unroll
        for (int kk = 0; kk < 4; kk++) {
            uint32_t a0[4], a1[4];
            LDSM_X4(a0, abase + kk * 32);
            LDSM_X4(a1, abase + kk * 32 + 16 * ASTR);
            const uint32_t bb = bbase + kk * 16 * BSTR;
            #pragma unroll
            for (int t = 0; t < 4; t += 2) {
                uint32_t bh[4];
                LDSM_X4T(bh, bb + t * 16);
                mma_f16(acc[0][t],     a0, bh);
                mma_f16(acc[0][t + 1], a0, bh + 2);
                mma_f16(acc[1][t],     a1, bh);
                mma_f16(acc[1][t + 1], a1, bh + 2);
            }
        }

        if (more) store_A(nxt, si4, sj4);        // regs -> SMEM after MMA

        buf = (buf == 2) ? 0 : buf + 1;
        nxt = (nxt == 2) ? 0 : nxt + 1;
    }

    // ---- epilogue: add fp32 bias (pair 0) and store ----
    float* op = out + (size_t)gm0 * OD;
    const int rr = lane >> 2;
    const int cc = (lane & 3) * 2;
    #pragma unroll
    for (int mt = 0; mt < 2; mt++) {
        #pragma unroll
        for (int nt = 0; nt < 4; nt++) {
            const int r0 = m0 + mt * 16 + rr;
            const int cn = n0 + nt * 8 + cc;
            const float b0 = g_bias[cn], b1 = g_bias[cn + 1];
            *(float2*)(op + (size_t)r0 * OD + cn) =
                make_float2(acc[mt][nt][0] + b0, acc[mt][nt][1] + b1);
            *(float2*)(op + (size_t)(r0 + 8) * OD + cn) =
                make_float2(acc[mt][nt][2] + b0, acc[mt][nt][3] + b1);
        }
    }
}

// ---------------------------------------------------------------------------
extern "C" void kernel_launch(void* const* d_in, const int* in_sizes, int n_in,
                              void* d_out, int out_size) {
    const float* in = (const float*)d_in[0];
    const float* wt = (const float*)d_in[1];
    if (n_in >= 2 && in_sizes[0] == NPAIRS * CH * OD) {
        const float* t = in; in = wt; wt = t;
    }
    float* out = (float*)d_out;

    prep_weights<<<(NPAIRS * CH * OD + 255) / 256, 256>>>(wt);
    prep_bias<<<1, OD>>>(wt);

    cudaFuncSetAttribute(qconv_pipe,
                         cudaFuncAttributeMaxDynamicSharedMemorySize, SMEM_TOTAL);
    qconv_pipe<<<NTILES, BDIM, SMEM_TOTAL>>>(in, out);
}